// round 11
// baseline (speedup 1.0000x reference)
#include <cuda_runtime.h>

// ---------------------------------------------------------------------------
// SSIM (16,3,512,512) fp32, 11x11 gaussian (sigma=1.5), zero padding.
// Round-11 (base R9 82.4us; R10's cp8 loader regressed -> reverted):
//  * planar cp16 loader (R9, 792 copies/block) + parity-interleaved (c,d):
//    pre-pass reads (a0,a1) from plane A slot s and (b0,b1) from plane B
//    slot s, writes (c0,d0)->A[s], (c1,d1)->B[s]  (read set == write set,
//    in-place, race-free). Even local cols' (c,d) in plane A, odd in B.
//  * consumer: taps split 6+5 across the two planes at consecutive slots ->
//    11 LDS.64 + 33 fma per row, no packs, no per-tap ALU (R9: 22 LDS.32 +
//    11 movs + 33 fma). ~20% fewer issue slots per row.
// ---------------------------------------------------------------------------

#define IMG_H 512
#define IMG_W 512
#define N_PLANES 48
#define N_BLOCKS (48 * 4 * 16)
#define TOTAL_PIX 12582912.0

#define GW0 0.26601172f
#define GW1 0.21300554f
#define GW2 0.10936069f
#define GW3 0.03600077f
#define GW4 0.00759876f
#define GW5 0.00102842f

__device__ double g_acc;
__device__ unsigned int g_count;

typedef unsigned long long u64;

__device__ __forceinline__ u64 pk2(float lo, float hi) {
    u64 r; asm("mov.b64 %0, {%1, %2};" : "=l"(r) : "f"(lo), "f"(hi)); return r;
}
__device__ __forceinline__ float2 upk2(u64 v) {
    float2 r; asm("mov.b64 {%0, %1}, %2;" : "=f"(r.x), "=f"(r.y) : "l"(v)); return r;
}
__device__ __forceinline__ u64 fma2(u64 a, u64 b, u64 c) {
    u64 d; asm("fma.rn.f32x2 %0, %1, %2, %3;" : "=l"(d) : "l"(a), "l"(b), "l"(c)); return d;
}
__device__ __forceinline__ u64 mul2(u64 a, u64 b) {
    u64 d; asm("mul.rn.f32x2 %0, %1, %2;" : "=l"(d) : "l"(a), "l"(b)); return d;
}
__device__ __forceinline__ void cp16(unsigned dst, const float* src, unsigned rs) {
    asm volatile("cp.async.cg.shared.global [%0], [%1], 16, %2;"
                 :: "r"(dst), "l"(src), "r"(rs));
}

// local cols 0..143  <->  global cols col0-8 .. col0+135
// thread tx's taps: local cols tx+3 .. tx+13 (max 140)
#define NSLOT   72                 // u64 slots per plane per row
#define PLANE_B (NSLOT * 8)        // 576 bytes
#define ROW_B   (2 * PLANE_B)      // 1152 bytes
#define BUF_B   (11 * ROW_B)       // 12672 bytes
#define NCP     36                 // 16B chunks per plane row
#define PRE_TASKS (11 * NSLOT)     // 792

__global__ __launch_bounds__(128, 7)
void ssim_kernel(const float* __restrict__ img1, const float* __restrict__ img2,
                 float* __restrict__ out) {
    const int plane = blockIdx.x;     // 0..47
    const int strip = blockIdx.y;     // 0..3
    const int band  = blockIdx.z;     // 0..15  (row bands of 32)
    const int tx    = threadIdx.x;

    const int col0 = strip * 128;
    const int row0 = band * 32;

    const float* __restrict__ p1 = img1 + (size_t)plane * (IMG_H * IMG_W);
    const float* __restrict__ p2 = img2 + (size_t)plane * (IMG_H * IMG_W);

    // [buf][row][plane A | plane B], u64 granularity
    __shared__ __align__(16) u64 smem[2][11][2 * NSLOT];

    unsigned sbase;
    asm("{ .reg .u64 t; cvta.to.shared.u64 t, %1; cvt.u32.u64 %0, t; }"
        : "=r"(sbase) : "l"((const void*)smem));

    // ---- loader (R9): thread tx<72 owns one 16B chunk column ----
    const int  larr  = (tx >= NCP) ? 1 : 0;
    const int  lpos  = tx - NCP * larr;
    const int  lgcol = col0 - 8 + lpos * 4;
    const bool lcolok = (tx < 2 * NCP) && ((unsigned)lgcol < (unsigned)IMG_W);
    const float* __restrict__ lbase = larr ? p2 : p1;
    const unsigned ldst = sbase + (unsigned)(larr * PLANE_B + lpos * 16);

    const u64 W2_0 = pk2(GW0, GW0), W2_1 = pk2(GW1, GW1), W2_2 = pk2(GW2, GW2);
    const u64 W2_3 = pk2(GW3, GW3), W2_4 = pk2(GW4, GW4), W2_5 = pk2(GW5, GW5);
    // vertical taps 0..10
    const u64 WT[11] = {W2_5, W2_4, W2_3, W2_2, W2_1, W2_0,
                        W2_1, W2_2, W2_3, W2_4, W2_5};
    // horizontal taps split by parity: even i = 0,2,4,6,8,10; odd i = 1,3,5,7,9
    const u64 WE[6] = {W2_5, W2_3, W2_1, W2_1, W2_3, W2_5};
    const u64 WO[5] = {W2_4, W2_2, W2_0, W2_2, W2_4};
    const u64 NEG1 = pk2(-1.f, -1.f);

    // consumer base offsets: taps at local cols m0,m0+2,... (even-i) and
    // m1,m1+2,... (odd-i); col m -> plane (m&1), slot m>>1.
    const int m0 = tx + 3, m1 = tx + 4;
    const unsigned offE = (unsigned)(((m0 & 1) ? PLANE_B : 0) + (m0 >> 1) * 8);
    const unsigned offO = (unsigned)(((m1 & 1) ? PLANE_B : 0) + (m1 >> 1) * 8);

    u64 ring01[11], ringq[11];
#pragma unroll
    for (int k = 0; k < 11; ++k) { ring01[k] = 0ull; ringq[k] = 0ull; }

    float acc = 0.f;
    const float C1  = 1e-4f;
    const float C2  = 9e-4f;
    const float C2E = 9e-4f + 1e-6f;

    auto load_chunk = [&](int t, int bb) {
        if (tx < 2 * NCP) {
            const int base = row0 - 5 + t * 11;
            const unsigned dbase = ldst + (unsigned)(bb * BUF_B);
#pragma unroll
            for (int r = 0; r < 11; ++r) {
                const int y = base + r;
                const bool ok = lcolok && ((unsigned)y < (unsigned)IMG_H);
                const int goff = ok ? (y * IMG_W + lgcol) : 0;
                cp16(dbase + (unsigned)(r * ROW_B), lbase + goff, ok ? 16u : 0u);
            }
        }
        asm volatile("cp.async.commit_group;");
    };

    load_chunk(0, 0);

    // input rows n = t*11 + k, 4 chunks; outputs for n in [10, 42)
    for (int t = 0; t < 4; ++t) {
        const int cur = t & 1;
        if (t < 3) {
            load_chunk(t + 1, cur ^ 1);
            asm volatile("cp.async.wait_group 1;");
        } else {
            asm volatile("cp.async.wait_group 0;");
        }
        __syncthreads();   // chunk t raw data visible

        // pre-pass: slot s of row r: A=(a0,a1), B=(b0,b1) ->
        //           A'=(a0+b0, a0-b0), B'=(a1+b1, a1-b1). In place, race-free.
        {
            u64* U = smem[cur][0];   // [11][144]
#pragma unroll 1
            for (int j = tx; j < PRE_TASKS; j += 128) {
                const int r = j / NSLOT;
                const int s = j - r * NSLOT;
                u64* pa = U + r * (2 * NSLOT) + s;
                u64* pb = pa + NSLOT;
                const float2 A = upk2(*pa);
                const float2 B = upk2(*pb);
                *pa = pk2(A.x + B.x, A.x - B.x);
                *pb = pk2(A.y + B.y, A.y - B.y);
            }
        }
        __syncthreads();   // (c,d) visible to all

#pragma unroll
        for (int k = 0; k < 11; ++k) {
            const char* rowp = (const char*)smem[cur][k];
            const u64* pe = (const u64*)(rowp + offE);
            const u64* po = (const u64*)(rowp + offO);
            u64 h01 = 0ull, hq = 0ull;
#pragma unroll
            for (int ii = 0; ii < 6; ++ii) {
                const u64 vv = pe[ii];             // LDS.64: (c,d), tap 2*ii
                const u64 w  = WE[ii];
                h01 = fma2(w, vv, h01);
                const u64 p = mul2(w, vv);
                hq  = fma2(p, vv, hq);
            }
#pragma unroll
            for (int ii = 0; ii < 5; ++ii) {
                const u64 vv = po[ii];             // tap 2*ii+1
                const u64 w  = WO[ii];
                h01 = fma2(w, vv, h01);
                const u64 p = mul2(w, vv);
                hq  = fma2(p, vv, hq);
            }
            ring01[k] = h01;
            ringq [k] = hq;

            const int n = t * 11 + k;
            if (n >= 10 && n < 42) {
                u64 m12 = 0ull, qv = 0ull;
#pragma unroll
                for (int j = 0; j < 11; ++j) {
                    const int s = (k + 1 + j) % 11;   // static after unroll
                    const u64 w = WT[j];
                    m12 = fma2(w, ring01[s], m12);    // (C, D)
                    qv  = fma2(w, ringq [s], qv);     // (Qc, Qd)
                }
                const u64 cd2 = mul2(m12, m12);           // (C^2, D^2)
                const u64 ev  = fma2(cd2, NEG1, qv);      // (Ec, Ed)
                const float2 s2 = upk2(cd2);
                const float2 e2 = upk2(ev);
                const float M = s2.x - s2.y;   // 4*mu1*mu2
                const float P = s2.x + s2.y;   // 2*(mu1^2+mu2^2)
                const float S = e2.x - e2.y;   // 4*sig12
                const float T = e2.x + e2.y;   // 2*sigpp
                const float num = fmaf(0.5f, M, C1) * fmaf(0.5f, S, C2);
                const float den = fmaf(0.5f, P, C1) * fmaf(0.5f, T, C2E);
                acc += __fdividef(num, den);
            }
        }
        __syncthreads();   // buffer cur free for chunk t+2's cp.async
    }

#pragma unroll
    for (int o = 16; o > 0; o >>= 1)
        acc += __shfl_xor_sync(0xFFFFFFFFu, acc, o);

    __shared__ float wsum[4];
    if ((tx & 31) == 0) wsum[tx >> 5] = acc;
    __syncthreads();

    if (tx == 0) {
        const float s = wsum[0] + wsum[1] + wsum[2] + wsum[3];
        atomicAdd(&g_acc, (double)s);
        __threadfence();
        const unsigned int done = atomicAdd(&g_count, 1u);
        if (done == (unsigned)(N_BLOCKS - 1)) {
            const double total = atomicAdd(&g_acc, 0.0);
            out[0] = (float)(total / TOTAL_PIX);
            g_acc = 0.0;
            g_count = 0u;
            __threadfence();
        }
    }
}

extern "C" void kernel_launch(void* const* d_in, const int* in_sizes, int n_in,
                              void* d_out, int out_size) {
    const float* img1 = (const float*)d_in[0];
    const float* img2 = (const float*)d_in[1];
    float* out = (float*)d_out;
    (void)in_sizes; (void)n_in; (void)out_size;

    dim3 grid(N_PLANES, 4, 16);
    ssim_kernel<<<grid, 128>>>(img1, img2, out);
}